// round 15
// baseline (speedup 1.0000x reference)
#include <cuda_runtime.h>
#include <cuda_fp16.h>

// CommNet forward: B=8192, N=64, D=128, O=16
//   H1 = tanh(wH1*obs); C1 = (sum_n H1 - H1)/(N-1)
//   H2 = tanh(wH2*H1 + wC2*C1) + obs ; out = H2 @ w_out + b_out
//
// One CTA per batch element, 128 threads (4 warps).
// Phase: thread = feature d; obs column read ONCE; x cached as half2[32]
//   (h2 is fp16 for the MMA anyway), h1 cached as half2[32]; pass2 arg is
//   linear in h1 -> 2 tanh/elem. fp32 tile [agent][d] (PITCHW=136),
//   conflict-free scalar column STS.
// GEMV via tensor cores: mma.m16n8k16 f16->f32. M=o(16), N=agents, K=d(128).
//   A = w^T fragments staged once in smem -> register-resident (32 regs).
//   B = h tile read ONCE as LDS.64 pairs + cvt f16x2. K-reduction inside MMA.
// R15: x in half2 cuts 32 regs; __launch_bounds__(128,5) -> 5 CTAs/SM.

#define N_AG 64
#define DIM  128
#define OUTD 16
#define PITCHW 136   // fp32 words per agent row (128 + 8 pad)

__device__ __forceinline__ float tanh_fast(float x) {
    float y; asm("tanh.approx.f32 %0, %1;" : "=f"(y) : "f"(x)); return y;
}
// pack (lo, hi) floats -> f16x2 register
__device__ __forceinline__ unsigned cvt_h2(float lo, float hi) {
    unsigned r;
    asm("cvt.rn.f16x2.f32 %0, %1, %2;" : "=r"(r) : "f"(hi), "f"(lo));
    return r;
}
__device__ __forceinline__ void mma16816(
    float& c0, float& c1, float& c2, float& c3,
    unsigned a0, unsigned a1, unsigned a2, unsigned a3,
    unsigned b0, unsigned b1)
{
    asm volatile(
        "mma.sync.aligned.m16n8k16.row.col.f32.f16.f16.f32 "
        "{%0,%1,%2,%3}, {%4,%5,%6,%7}, {%8,%9}, {%0,%1,%2,%3};"
        : "+f"(c0), "+f"(c1), "+f"(c2), "+f"(c3)
        : "r"(a0), "r"(a1), "r"(a2), "r"(a3), "r"(b0), "r"(b1));
}

__global__ __launch_bounds__(128, 5)
void commnet_kernel(const float* __restrict__ obs,
                    const float* __restrict__ wH1,
                    const float* __restrict__ wH2,
                    const float* __restrict__ wC2,
                    const float* __restrict__ wout,
                    const float* __restrict__ bout,
                    float* __restrict__ out)
{
    __shared__ __align__(16) float    sh[N_AG * PITCHW];   // 34,816 B h2 tile
    __shared__ __align__(16) unsigned wfrag[8 * 32 * 4];   //  4,096 B A-frags

    const int tid = threadIdx.x;                 // = feature d for phase
    const int b   = blockIdx.x;

    // ---- stage A-fragments of w^T (frag-order; 2 slots per thread) ----
    {
        const int s  = tid >> 4;
        const int l0 = (tid & 15) * 2;
        #pragma unroll
        for (int e = 0; e < 2; e++) {
            const int l = l0 + e;
            const int g = l >> 2, tg = l & 3;
            const int d0 = 16 * s + 2 * tg;
            uint4 v;
            v.x = cvt_h2(wout[d0 * OUTD + g],           wout[(d0 + 1) * OUTD + g]);
            v.y = cvt_h2(wout[d0 * OUTD + g + 8],       wout[(d0 + 1) * OUTD + g + 8]);
            v.z = cvt_h2(wout[(d0 + 8) * OUTD + g],     wout[(d0 + 9) * OUTD + g]);
            v.w = cvt_h2(wout[(d0 + 8) * OUTD + g + 8], wout[(d0 + 9) * OUTD + g + 8]);
            *(uint4*)&wfrag[(s * 32 + l) * 4] = v;
        }
    }

    const float a1c = wH1[tid];
    const float a2c = wH2[tid];
    const float c2c = wC2[tid];

    // ---- pass 1: stream obs column ONCE; cache x and h1 as half2 ----
    const float* ob = obs + (size_t)b * (N_AG * DIM) + tid;
    half2 xh[N_AG / 2];
    half2 h1h[N_AG / 2];
    float sum = 0.0f;
    #pragma unroll
    for (int k = 0; k < N_AG / 2; k++) {
        float xa = ob[(2 * k) * DIM];
        float xb = ob[(2 * k + 1) * DIM];
        float ha = tanh_fast(a1c * xa);
        float hb = tanh_fast(a1c * xb);
        sum += ha + hb;
        xh[k]  = __floats2half2_rn(xa, xb);
        h1h[k] = __floats2half2_rn(ha, hb);
    }
    const float inv   = 1.0f / (float)(N_AG - 1);
    const float alpha = a2c - c2c * inv;         // arg = alpha*h1 + beta
    const float beta  = c2c * inv * sum;

    // ---- pass 2: h2 -> tile COLUMN d (scalar STS.32, conflict-free) ----
    #pragma unroll
    for (int k = 0; k < N_AG / 2; k++) {
        float2 f  = __half22float2(h1h[k]);
        float2 xf = __half22float2(xh[k]);
        float h2a = tanh_fast(alpha * f.x + beta) + xf.x;
        float h2b = tanh_fast(alpha * f.y + beta) + xf.y;
        sh[(2 * k) * PITCHW + tid]     = h2a;
        sh[(2 * k + 1) * PITCHW + tid] = h2b;
    }
    __syncthreads();

    // ---- tensor-core GEMV: warp = 16 agents (2 n-tiles), K=128 in 8 steps ----
    const int wid  = tid >> 5;
    const int lane = tid & 31;
    const int g    = lane >> 2;                  // 0..7
    const int tg   = lane & 3;                   // 0..3

    unsigned af[8][4];
    #pragma unroll
    for (int s = 0; s < 8; s++) {
        uint4 v = *(const uint4*)&wfrag[(s * 32 + lane) * 4];
        af[s][0] = v.x; af[s][1] = v.y; af[s][2] = v.z; af[s][3] = v.w;
    }
    const float bg  = bout[g];
    const float bg8 = bout[g + 8];

    float* op = out + (size_t)b * (N_AG * OUTD);

    #pragma unroll
    for (int nt = 0; nt < 2; nt++) {
        const int abase = wid * 16 + nt * 8;     // 8 agents per n-tile
        float c0 = bg, c1 = bg, c2 = bg8, c3 = bg8;
        const float* hb = &sh[(abase + g) * PITCHW + 2 * tg];
        #pragma unroll
        for (int s = 0; s < 8; s++) {
            float2 f0 = *(const float2*)&hb[16 * s];       // k = 16s+2tg, +1
            float2 f1 = *(const float2*)&hb[16 * s + 8];   // k = +8, +9
            unsigned b0 = cvt_h2(f0.x, f0.y);
            unsigned b1 = cvt_h2(f1.x, f1.y);
            mma16816(c0, c1, c2, c3,
                     af[s][0], af[s][1], af[s][2], af[s][3], b0, b1);
        }
        // D[o][agent]: c0=(g,2tg) c1=(g,2tg+1) c2=(g+8,2tg) c3=(g+8,2tg+1)
        op[(abase + 2 * tg) * OUTD + g]         = c0;
        op[(abase + 2 * tg + 1) * OUTD + g]     = c1;
        op[(abase + 2 * tg) * OUTD + g + 8]     = c2;
        op[(abase + 2 * tg + 1) * OUTD + g + 8] = c3;
    }
}

extern "C" void kernel_launch(void* const* d_in, const int* in_sizes, int n_in,
                              void* d_out, int out_size) {
    const float* obs  = (const float*)d_in[0];
    const float* wH1  = (const float*)d_in[1];
    // d_in[2] = w_C1: multiplies C0 = 0 -> unused
    const float* wH2  = (const float*)d_in[3];
    const float* wC2  = (const float*)d_in[4];
    const float* wout = (const float*)d_in[5];
    const float* bout = (const float*)d_in[6];
    float* out = (float*)d_out;

    int B = in_sizes[0] / (N_AG * DIM);   // 8192
    commnet_kernel<<<B, 128>>>(obs, wH1, wH2, wC2, wout, bout, out);
}

// round 16
// speedup vs baseline: 1.0666x; 1.0666x over previous
#include <cuda_runtime.h>
#include <cuda_fp16.h>

// CommNet forward: B=8192, N=64, D=128, O=16
//   H1 = tanh(wH1*obs); C1 = (sum_n H1 - H1)/(N-1)
//   H2 = tanh(wH2*H1 + wC2*C1) + obs ; out = H2 @ w_out + b_out
//
// One CTA per batch element, 128 threads (4 warps).
// Phase (R14-proven): thread = feature d; x[64] fp32 regs; h1 cached half2;
//   pass2 arg linear in h1 -> 2 tanh/elem.
// R16: h2 tile stored as FP16 [agent][d] (PITCH_H=136 halves):
//   - B-fragment load = single LDS.32 (1 wavefront, conflict-free), no cvt
//   - same rn rounding as R14's read-side cvt -> numerically identical
// GEMV via tensor cores: mma.m16n8k16 f16->f32; A = w^T frags register-
//   resident; K-reduction inside MMA; single __syncthreads.

#define N_AG 64
#define DIM  128
#define OUTD 16
#define PITCH_H 136   // halves per agent row; 68 words ≡ 4 mod 32 -> conflict-free

__device__ __forceinline__ float tanh_fast(float x) {
    float y; asm("tanh.approx.f32 %0, %1;" : "=f"(y) : "f"(x)); return y;
}
// pack (lo, hi) floats -> f16x2 register (lo in low half)
__device__ __forceinline__ unsigned cvt_h2(float lo, float hi) {
    unsigned r;
    asm("cvt.rn.f16x2.f32 %0, %1, %2;" : "=r"(r) : "f"(hi), "f"(lo));
    return r;
}
__device__ __forceinline__ void mma16816(
    float& c0, float& c1, float& c2, float& c3,
    unsigned a0, unsigned a1, unsigned a2, unsigned a3,
    unsigned b0, unsigned b1)
{
    asm volatile(
        "mma.sync.aligned.m16n8k16.row.col.f32.f16.f16.f32 "
        "{%0,%1,%2,%3}, {%4,%5,%6,%7}, {%8,%9}, {%0,%1,%2,%3};"
        : "+f"(c0), "+f"(c1), "+f"(c2), "+f"(c3)
        : "r"(a0), "r"(a1), "r"(a2), "r"(a3), "r"(b0), "r"(b1));
}

__global__ __launch_bounds__(128, 4)
void commnet_kernel(const float* __restrict__ obs,
                    const float* __restrict__ wH1,
                    const float* __restrict__ wH2,
                    const float* __restrict__ wC2,
                    const float* __restrict__ wout,
                    const float* __restrict__ bout,
                    float* __restrict__ out)
{
    __shared__ __align__(16) __half   shh[N_AG * PITCH_H];  // 17,408 B h2 tile
    __shared__ __align__(16) unsigned wfrag[8 * 32 * 4];    //  4,096 B A-frags

    const int tid = threadIdx.x;                 // = feature d for phase
    const int b   = blockIdx.x;

    // ---- stage A-fragments of w^T (frag-order; 2 slots per thread) ----
    {
        const int s  = tid >> 4;
        const int l0 = (tid & 15) * 2;
        #pragma unroll
        for (int e = 0; e < 2; e++) {
            const int l = l0 + e;
            const int g = l >> 2, tg = l & 3;
            const int d0 = 16 * s + 2 * tg;
            uint4 v;
            v.x = cvt_h2(wout[d0 * OUTD + g],           wout[(d0 + 1) * OUTD + g]);
            v.y = cvt_h2(wout[d0 * OUTD + g + 8],       wout[(d0 + 1) * OUTD + g + 8]);
            v.z = cvt_h2(wout[(d0 + 8) * OUTD + g],     wout[(d0 + 9) * OUTD + g]);
            v.w = cvt_h2(wout[(d0 + 8) * OUTD + g + 8], wout[(d0 + 9) * OUTD + g + 8]);
            *(uint4*)&wfrag[(s * 32 + l) * 4] = v;
        }
    }

    // ---- obs column d=tid into registers: 64 coalesced LDG.32 (read ONCE) ----
    const float* ob = obs + (size_t)b * (N_AG * DIM) + tid;
    float x[N_AG];
    #pragma unroll
    for (int n = 0; n < N_AG; n++)
        x[n] = ob[n * DIM];

    const float a1c = wH1[tid];
    const float a2c = wH2[tid];
    const float c2c = wC2[tid];

    // ---- pass 1: h1 = tanh(a1*x); cache half2; accumulate sum ----
    half2 h1h[N_AG / 2];
    float sum = 0.0f;
    #pragma unroll
    for (int k = 0; k < N_AG / 2; k++) {
        float ha = tanh_fast(a1c * x[2 * k]);
        float hb = tanh_fast(a1c * x[2 * k + 1]);
        sum += ha + hb;
        h1h[k] = __floats2half2_rn(ha, hb);
    }
    const float inv   = 1.0f / (float)(N_AG - 1);
    const float alpha = a2c - c2c * inv;         // arg = alpha*h1 + beta
    const float beta  = c2c * inv * sum;

    // ---- pass 2: h2 (fp32) -> FP16 tile column d (STS.16, contiguous/warp) ----
    #pragma unroll
    for (int k = 0; k < N_AG / 2; k++) {
        float2 f = __half22float2(h1h[k]);
        float h2a = tanh_fast(alpha * f.x + beta) + x[2 * k];
        float h2b = tanh_fast(alpha * f.y + beta) + x[2 * k + 1];
        shh[(2 * k) * PITCH_H + tid]     = __float2half_rn(h2a);
        shh[(2 * k + 1) * PITCH_H + tid] = __float2half_rn(h2b);
    }
    __syncthreads();

    // ---- tensor-core GEMV: warp = 16 agents (2 n-tiles), K=128 in 8 steps ----
    const int wid  = tid >> 5;
    const int lane = tid & 31;
    const int g    = lane >> 2;                  // 0..7
    const int tg   = lane & 3;                   // 0..3

    unsigned af[8][4];
    #pragma unroll
    for (int s = 0; s < 8; s++) {
        uint4 v = *(const uint4*)&wfrag[(s * 32 + lane) * 4];
        af[s][0] = v.x; af[s][1] = v.y; af[s][2] = v.z; af[s][3] = v.w;
    }
    const float bg  = bout[g];
    const float bg8 = bout[g + 8];

    float* op = out + (size_t)b * (N_AG * OUTD);

    #pragma unroll
    for (int nt = 0; nt < 2; nt++) {
        const int abase = wid * 16 + nt * 8;     // 8 agents per n-tile
        float c0 = bg, c1 = bg, c2 = bg8, c3 = bg8;
        // B-frag: row n = abase+g, k-pairs (16s+2tg, +1) and (+8, +9)
        const __half* hb = &shh[(abase + g) * PITCH_H + 2 * tg];
        #pragma unroll
        for (int s = 0; s < 8; s++) {
            unsigned b0 = *(const unsigned*)&hb[16 * s];       // f16x2, lo = k
            unsigned b1 = *(const unsigned*)&hb[16 * s + 8];
            mma16816(c0, c1, c2, c3,
                     af[s][0], af[s][1], af[s][2], af[s][3], b0, b1);
        }
        // D[o][agent]: c0=(g,2tg) c1=(g,2tg+1) c2=(g+8,2tg) c3=(g+8,2tg+1)
        op[(abase + 2 * tg) * OUTD + g]         = c0;
        op[(abase + 2 * tg + 1) * OUTD + g]     = c1;
        op[(abase + 2 * tg) * OUTD + g + 8]     = c2;
        op[(abase + 2 * tg + 1) * OUTD + g + 8] = c3;
    }
}

extern "C" void kernel_launch(void* const* d_in, const int* in_sizes, int n_in,
                              void* d_out, int out_size) {
    const float* obs  = (const float*)d_in[0];
    const float* wH1  = (const float*)d_in[1];
    // d_in[2] = w_C1: multiplies C0 = 0 -> unused
    const float* wH2  = (const float*)d_in[3];
    const float* wC2  = (const float*)d_in[4];
    const float* wout = (const float*)d_in[5];
    const float* bout = (const float*)d_in[6];
    float* out = (float*)d_out;

    int B = in_sizes[0] / (N_AG * DIM);   // 8192
    commnet_kernel<<<B, 128>>>(obs, wH1, wH2, wC2, wout, bout, out);
}